// round 6
// baseline (speedup 1.0000x reference)
#include <cuda_runtime.h>
#include <cstdint>

#define N_NODES 100000
#define E_EDGES 1280000
#define M_PAD   100096              // N rounded up to 128
#define C_IN    64
#define MID     256
#define OUT_F   64
#define BN_EPS  1e-5f

// ---------------- scratch (static device memory) ---------------------------
// zero-region (single memset): cnt[N] | off[N] | colsum[256] | colsq[256]
__device__ unsigned int g_zero[2 * N_NODES + 512];
#define P_CNT()    ((int*)g_zero)
#define P_OFF()    (((int*)g_zero) + N_NODES)
#define P_COLSUM() ((float*)(((int*)g_zero) + 2 * N_NODES))
#define P_COLSQ()  ((float*)(((int*)g_zero) + 2 * N_NODES + 256))

__device__ int   g_start[N_NODES + 1];            // CSR offsets
__device__ int2  g_edge[E_EDGES];                 // row-sorted (col, attr-bits)
__device__ float g_hT[(size_t)MID * M_PAD];       // h transposed [MID][M_PAD]
__device__ float g_W2p[MID * OUT_F];              // s-scaled W2
__device__ float g_b2p[OUT_F];

// ---------------- packed fp32 helpers (Blackwell FFMA2) --------------------
__device__ __forceinline__ unsigned long long dup2(float v) {
    unsigned long long r;
    asm("mov.b64 %0, {%1, %1};" : "=l"(r) : "f"(v));
    return r;
}
__device__ __forceinline__ void ffma2(unsigned long long& d,
                                      unsigned long long a,
                                      unsigned long long b) {
    asm("fma.rn.f32x2 %0, %1, %2, %0;" : "+l"(d) : "l"(a), "l"(b));
}
__device__ __forceinline__ void unpack2(unsigned long long v, float& lo, float& hi) {
    asm("mov.b64 {%0, %1}, %2;" : "=f"(lo), "=f"(hi) : "l"(v));
}

// ---------------- per-block dtype detection --------------------------------
// int64 node ids < 2^31 little-endian => odd 32-bit words all zero.
__device__ __forceinline__ int detect_idx64_block(const int* ei32, int* sflag) {
    if (threadIdx.x == 0) {
        int all_zero = 1;
        #pragma unroll
        for (int i = 0; i < 16; i++)
            if (ei32[2 * i + 1] != 0) all_zero = 0;
        *sflag = all_zero;
    }
    __syncthreads();
    return *sflag;
}

__device__ __forceinline__ int load_idx(const void* ei, size_t pos, int idx64) {
    return idx64 ? (int)((const long long*)ei)[pos] : ((const int*)ei)[pos];
}

// ---------------- 1) histogram --------------------------------------------
__global__ void hist_kernel(const void* __restrict__ ei) {
    __shared__ int sflag;
    int idx64 = detect_idx64_block((const int*)ei, &sflag);
    int e = blockIdx.x * blockDim.x + threadIdx.x;
    if (e >= E_EDGES) return;
    int row = load_idx(ei, e, idx64);
    if ((unsigned)row < N_NODES) atomicAdd(&P_CNT()[row], 1);
}

// ---------------- 2) single-block exclusive scan ---------------------------
__global__ __launch_bounds__(1024)
void scan_kernel() {
    __shared__ int wsum[32], woff[32];
    __shared__ int carry_s, wtot_s;
    int tid = threadIdx.x, lane = tid & 31, wid = tid >> 5;
    if (tid == 0) carry_s = 0;
    __syncthreads();
    const int* cnt = P_CNT();
    #pragma unroll 1
    for (int c = 0; c < 25; c++) {          // 25 * 4096 = 102400 >= 100000
        int base = c * 4096 + tid * 4;
        int4 v;
        v.x = (base     < N_NODES) ? cnt[base]     : 0;
        v.y = (base + 1 < N_NODES) ? cnt[base + 1] : 0;
        v.z = (base + 2 < N_NODES) ? cnt[base + 2] : 0;
        v.w = (base + 3 < N_NODES) ? cnt[base + 3] : 0;
        int s = v.x + v.y + v.z + v.w;
        int p = s;
        #pragma unroll
        for (int o = 1; o < 32; o <<= 1) {
            int t = __shfl_up_sync(0xFFFFFFFFu, p, o);
            if (lane >= o) p += t;
        }
        if (lane == 31) wsum[wid] = p;
        __syncthreads();
        if (wid == 0) {
            int t = wsum[lane];
            int q = t;
            #pragma unroll
            for (int o = 1; o < 32; o <<= 1) {
                int u = __shfl_up_sync(0xFFFFFFFFu, q, o);
                if (lane >= o) q += u;
            }
            woff[lane] = q - t;
            if (lane == 31) wtot_s = q;
        }
        __syncthreads();
        int excl = carry_s + woff[wid] + (p - s);
        if (base     < N_NODES) g_start[base]     = excl;
        if (base + 1 < N_NODES) g_start[base + 1] = excl + v.x;
        if (base + 2 < N_NODES) g_start[base + 2] = excl + v.x + v.y;
        if (base + 3 < N_NODES) g_start[base + 3] = excl + v.x + v.y + v.z;
        __syncthreads();
        if (tid == 0) carry_s += wtot_s;
        __syncthreads();
    }
    if (tid == 0) g_start[N_NODES] = carry_s;
}

// ---------------- 3) scatter into row-sorted order (packed int2) -----------
__global__ void scatter_kernel(const void* __restrict__ ei,
                               const float* __restrict__ ea) {
    __shared__ int sflag;
    int idx64 = detect_idx64_block((const int*)ei, &sflag);
    int e = blockIdx.x * blockDim.x + threadIdx.x;
    if (e >= E_EDGES) return;
    int row = load_idx(ei, e, idx64);
    int col = load_idx(ei, (size_t)E_EDGES + e, idx64);
    if ((unsigned)row >= N_NODES || (unsigned)col >= N_NODES) return;
    int p = g_start[row] + atomicAdd(&P_OFF()[row], 1);
    g_edge[p] = make_int2(col, __float_as_int(ea[e]));
}

// ---------------- 4) FUSED gather + GEMM1 ----------------------------------
// One block = 128 nodes x ALL 256 output columns. 512 threads.
// Phase A: 16 warps gather 8 nodes each (CSR walk, mean) -> transposed As.
// Phase B: FFMA2 mainloop, K=128. Epilogue: +b1, relu, BN stats,
//          transposed store of h into g_hT.
#define G1_SMEM_FLOATS (128*132 + 128*256)
__global__ __launch_bounds__(512, 1)
void gemm1_fused_kernel(const float* __restrict__ x,
                        const float* __restrict__ W1,
                        const float* __restrict__ b1) {
    extern __shared__ float sm[];
    float* As = sm;               // [k=128][m pitch 132]
    float* Bs = sm + 128 * 132;   // [k=128][n=256]
    __shared__ float ssum[256], ssq[256];

    int tid = threadIdx.x;
    int warp = tid >> 5, lane = tid & 31;
    int rowbase = blockIdx.x * 128;

    if (tid < 256) { ssum[tid] = 0.f; ssq[tid] = 0.f; }

    // B: full W1 [128][256], float4 copy (conflict-free, coalesced)
    #pragma unroll
    for (int i = 0; i < 16; i++) {
        int idx = i * 512 + tid;          // 8192 float4
        *(float4*)&Bs[idx * 4] = *(const float4*)&W1[(size_t)idx * 4];
    }

    // Phase A: gather. Warp w handles nodes w*8 .. w*8+7.
    #pragma unroll 1
    for (int t = 0; t < 8; t++) {
        int local = warp * 8 + t;
        int r = rowbase + local;
        float v0a = 0.f, v1a = 0.f, w0a = 0.f, w1a = 0.f;
        float v0b = 0.f, v1b = 0.f, w0b = 0.f, w1b = 0.f;
        float inv = 0.f;
        if (r < N_NODES) {
            int s = g_start[r];
            int e = g_start[r + 1];
            for (int base = s; base < e; base += 32) {
                int rem = e - base;
                int2 ed = make_int2(0, 0);
                if (lane < rem) ed = g_edge[base + lane];
                int n = rem < 32 ? rem : 32;
                int j = 0;
                #pragma unroll 1
                for (; j + 4 <= n; j += 4) {
                    int   c0 = __shfl_sync(0xFFFFFFFFu, ed.x, j);
                    float a0 = __int_as_float(__shfl_sync(0xFFFFFFFFu, ed.y, j));
                    int   c1 = __shfl_sync(0xFFFFFFFFu, ed.x, j + 1);
                    float a1 = __int_as_float(__shfl_sync(0xFFFFFFFFu, ed.y, j + 1));
                    int   c2 = __shfl_sync(0xFFFFFFFFu, ed.x, j + 2);
                    float a2 = __int_as_float(__shfl_sync(0xFFFFFFFFu, ed.y, j + 2));
                    int   c3 = __shfl_sync(0xFFFFFFFFu, ed.x, j + 3);
                    float a3 = __int_as_float(__shfl_sync(0xFFFFFFFFu, ed.y, j + 3));
                    const float* x0p = x + (size_t)c0 * C_IN;
                    const float* x1p = x + (size_t)c1 * C_IN;
                    const float* x2p = x + (size_t)c2 * C_IN;
                    const float* x3p = x + (size_t)c3 * C_IN;
                    float p00 = x0p[lane], p01 = x0p[lane + 32];
                    float p10 = x1p[lane], p11 = x1p[lane + 32];
                    float p20 = x2p[lane], p21 = x2p[lane + 32];
                    float p30 = x3p[lane], p31 = x3p[lane + 32];
                    v0a += p00; v1a += p01; w0a = fmaf(p00, a0, w0a); w1a = fmaf(p01, a0, w1a);
                    v0b += p10; v1b += p11; w0b = fmaf(p10, a1, w0b); w1b = fmaf(p11, a1, w1b);
                    v0a += p20; v1a += p21; w0a = fmaf(p20, a2, w0a); w1a = fmaf(p21, a2, w1a);
                    v0b += p30; v1b += p31; w0b = fmaf(p30, a3, w0b); w1b = fmaf(p31, a3, w1b);
                }
                #pragma unroll 1
                for (; j < n; j++) {
                    int   c = __shfl_sync(0xFFFFFFFFu, ed.x, j);
                    float a = __int_as_float(__shfl_sync(0xFFFFFFFFu, ed.y, j));
                    const float* xr = x + (size_t)c * C_IN;
                    float p0 = xr[lane], p1 = xr[lane + 32];
                    v0a += p0; v1a += p1;
                    w0a = fmaf(p0, a, w0a); w1a = fmaf(p1, a, w1a);
                }
            }
            inv = 1.f / fmaxf((float)(e - s), 1.f);
        }
        As[lane * 132 + local]        = (v0a + v0b) * inv;
        As[(lane + 32) * 132 + local] = (v1a + v1b) * inv;
        As[(lane + 64) * 132 + local] = (w0a + w0b) * inv;
        As[(lane + 96) * 132 + local] = (w1a + w1b) * inv;
    }
    __syncthreads();

    // Phase B: mainloop. Warps 4(M) x 4(N); thread tile 8x8.
    int warpM = warp & 3, warpN = warp >> 2;
    int mp = lane >> 3,  np = lane & 7;
    int tm = warpM * 32 + mp * 8;
    int tn = warpN * 64 + np * 8;

    unsigned long long acc2[4][8];
    #pragma unroll
    for (int i = 0; i < 4; i++)
        #pragma unroll
        for (int j = 0; j < 8; j++) acc2[i][j] = 0ull;

    #pragma unroll 4
    for (int k = 0; k < 128; k++) {
        ulonglong2 A0 = *(const ulonglong2*)&As[k * 132 + tm];
        ulonglong2 A1 = *(const ulonglong2*)&As[k * 132 + tm + 4];
        unsigned long long ap[4] = {A0.x, A0.y, A1.x, A1.y};
        float4 b0 = *(const float4*)&Bs[k * 256 + tn];
        float4 b1v = *(const float4*)&Bs[k * 256 + tn + 4];
        unsigned long long bp[8] = {dup2(b0.x), dup2(b0.y), dup2(b0.z), dup2(b0.w),
                                    dup2(b1v.x), dup2(b1v.y), dup2(b1v.z), dup2(b1v.w)};
        #pragma unroll
        for (int i = 0; i < 4; i++)
            #pragma unroll
            for (int j = 0; j < 8; j++) ffma2(acc2[i][j], ap[i], bp[j]);
    }

    float acc[8][8];
    #pragma unroll
    for (int i = 0; i < 4; i++)
        #pragma unroll
        for (int j = 0; j < 8; j++)
            unpack2(acc2[i][j], acc[2 * i][j], acc[2 * i + 1][j]);

    float bb[8];
    #pragma unroll
    for (int j = 0; j < 8; j++) bb[j] = b1[tn + j];

    #pragma unroll
    for (int i = 0; i < 8; i++)
        #pragma unroll
        for (int j = 0; j < 8; j++)
            acc[i][j] = fmaxf(acc[i][j] + bb[j], 0.f);

    // transposed store (pad rows >= N written too; harmless)
    #pragma unroll
    for (int j = 0; j < 8; j++) {
        size_t cb = (size_t)(tn + j) * M_PAD + rowbase + tm;
        *(float4*)&g_hT[cb]     = make_float4(acc[0][j], acc[1][j], acc[2][j], acc[3][j]);
        *(float4*)&g_hT[cb + 4] = make_float4(acc[4][j], acc[5][j], acc[6][j], acc[7][j]);
    }

    // BN stats over valid rows only
    float s_[8], q_[8];
    #pragma unroll
    for (int j = 0; j < 8; j++) { s_[j] = 0.f; q_[j] = 0.f; }
    #pragma unroll
    for (int i = 0; i < 8; i++) {
        if (rowbase + tm + i < N_NODES) {
            #pragma unroll
            for (int j = 0; j < 8; j++) {
                s_[j] += acc[i][j];
                q_[j] += acc[i][j] * acc[i][j];
            }
        }
    }
    #pragma unroll
    for (int j = 0; j < 8; j++) {
        s_[j] += __shfl_xor_sync(0xFFFFFFFFu, s_[j], 8);
        s_[j] += __shfl_xor_sync(0xFFFFFFFFu, s_[j], 16);
        q_[j] += __shfl_xor_sync(0xFFFFFFFFu, q_[j], 8);
        q_[j] += __shfl_xor_sync(0xFFFFFFFFu, q_[j], 16);
    }
    if (mp == 0) {
        #pragma unroll
        for (int j = 0; j < 8; j++) {
            atomicAdd(&ssum[tn + j], s_[j]);
            atomicAdd(&ssq[tn + j],  q_[j]);
        }
    }
    __syncthreads();
    if (tid < 256) {
        atomicAdd(&P_COLSUM()[tid], ssum[tid]);
        atomicAdd(&P_COLSQ()[tid],  ssq[tid]);
    }
}

// ---------------- finalize: BN fold into W2', b2' --------------------------
__global__ void finalize_kernel(const float* __restrict__ gamma,
                                const float* __restrict__ beta,
                                const float* __restrict__ W2,
                                const float* __restrict__ b2) {
    __shared__ float s_sm[MID], t_sm[MID];
    int tid = threadIdx.x;  // 256
    float mu  = P_COLSUM()[tid] * (1.f / N_NODES);
    float var = P_COLSQ()[tid]  * (1.f / N_NODES) - mu * mu;
    float s = gamma[tid] * rsqrtf(var + BN_EPS);
    float t = beta[tid] - mu * s;
    s_sm[tid] = s; t_sm[tid] = t;
    __syncthreads();
    #pragma unroll
    for (int i = 0; i < 64; i++) {
        int idx = i * 256 + tid;            // 16384 = 256x64
        g_W2p[idx] = W2[idx] * s_sm[idx >> 6];
    }
    if (tid < OUT_F) {
        float acc = b2[tid];
        for (int j = 0; j < MID; j++) acc += t_sm[j] * W2[j * OUT_F + tid];
        g_b2p[tid] = acc;
    }
}

// ---------------- GEMM2: out = h @ W2p + b2p (A from g_hT, direct copy) ----
#define G2_SMEM_FLOATS (256*128 + 256*64 + 64)
__global__ __launch_bounds__(256, 1)
void gemm2_kernel(float* __restrict__ out) {
    extern __shared__ float sm[];
    float* As = sm;               // [k=256][m=128] pitch 128
    float* Bs = sm + 256 * 128;   // [k=256][n=64]
    float* bb = Bs + 256 * 64;    // [64]
    int tid = threadIdx.x;
    int rowbase = blockIdx.x * 128;

    #pragma unroll
    for (int i = 0; i < 32; i++) {
        int idx = i * 256 + tid;          // 8192 float4 = 256x128 floats
        int k  = idx >> 5;
        int m4 = idx & 31;
        *(float4*)&As[k * 128 + m4 * 4] =
            *(const float4*)&g_hT[(size_t)k * M_PAD + rowbase + m4 * 4];
    }
    #pragma unroll
    for (int i = 0; i < 16; i++) {
        int idx = i * 256 + tid;
        *(float4*)&Bs[idx * 4] = *(const float4*)&g_W2p[idx * 4];
    }
    if (tid < OUT_F) bb[tid] = g_b2p[tid];
    __syncthreads();

    int warp = tid >> 5, lane = tid & 31;
    int warpM = warp & 3, warpN = warp >> 2;
    int mp = lane >> 3,  np = lane & 7;
    int tm = warpM * 32 + mp * 8;
    int tn = warpN * 32 + np * 4;

    unsigned long long acc2[4][4];
    #pragma unroll
    for (int i = 0; i < 4; i++)
        #pragma unroll
        for (int j = 0; j < 4; j++) acc2[i][j] = 0ull;

    #pragma unroll 4
    for (int k = 0; k < 256; k++) {
        ulonglong2 A0 = *(const ulonglong2*)&As[k * 128 + tm];
        ulonglong2 A1 = *(const ulonglong2*)&As[k * 128 + tm + 4];
        unsigned long long ap[4] = {A0.x, A0.y, A1.x, A1.y};
        float4 b0 = *(const float4*)&Bs[k * 64 + tn];
        unsigned long long bp[4] = {dup2(b0.x), dup2(b0.y), dup2(b0.z), dup2(b0.w)};
        #pragma unroll
        for (int i = 0; i < 4; i++)
            #pragma unroll
            for (int j = 0; j < 4; j++) ffma2(acc2[i][j], ap[i], bp[j]);
    }

    float acc[8][4];
    #pragma unroll
    for (int i = 0; i < 4; i++)
        #pragma unroll
        for (int j = 0; j < 4; j++)
            unpack2(acc2[i][j], acc[2 * i][j], acc[2 * i + 1][j]);

    float4 bv = make_float4(bb[tn], bb[tn + 1], bb[tn + 2], bb[tn + 3]);
    #pragma unroll
    for (int i = 0; i < 8; i++) {
        int r = rowbase + tm + i;
        if (r < N_NODES) {
            float4 o = make_float4(acc[i][0] + bv.x, acc[i][1] + bv.y,
                                   acc[i][2] + bv.z, acc[i][3] + bv.w);
            *(float4*)&out[(size_t)r * OUT_F + tn] = o;
        }
    }
}

// ---------------- launch ---------------------------------------------------
extern "C" void kernel_launch(void* const* d_in, const int* in_sizes, int n_in,
                              void* d_out, int out_size) {
    int ix = -1, iei = -1, iea = -1, iW1 = -1, iW2 = -1, ib2 = -1;
    int p256[3]; int n256 = 0;
    for (int i = 0; i < n_in; i++) {
        switch (in_sizes[i]) {
            case 6400000: ix  = i; break;
            case 2560000: iei = i; break;
            case 1280000: iea = i; break;
            case 32768:   iW1 = i; break;
            case 16384:   iW2 = i; break;
            case 64:      ib2 = i; break;
            case 256:     if (n256 < 3) p256[n256++] = i; break;
            default: break;
        }
    }
    int ib1, igamma, ibeta;
    if (n_in > 0 && in_sizes[0] == 6400000) { ib1 = p256[0]; igamma = p256[1]; ibeta = p256[2]; }
    else                                    { ib1 = p256[0]; ibeta  = p256[1]; igamma = p256[2]; }

    const float* x     = (const float*)d_in[ix];
    const void*  ei    = d_in[iei];
    const float* ea    = (const float*)d_in[iea];
    const float* W1    = (const float*)d_in[iW1];
    const float* b1    = (const float*)d_in[ib1];
    const float* gamma = (const float*)d_in[igamma];
    const float* beta  = (const float*)d_in[ibeta];
    const float* W2    = (const float*)d_in[iW2];
    const float* b2    = (const float*)d_in[ib2];
    float* out = (float*)d_out;

    cudaFuncSetAttribute(gemm1_fused_kernel, cudaFuncAttributeMaxDynamicSharedMemorySize,
                         G1_SMEM_FLOATS * (int)sizeof(float));
    cudaFuncSetAttribute(gemm2_kernel, cudaFuncAttributeMaxDynamicSharedMemorySize,
                         G2_SMEM_FLOATS * (int)sizeof(float));

    void* p;
    cudaGetSymbolAddress(&p, g_zero);
    cudaMemsetAsync(p, 0, sizeof(unsigned int) * (2 * N_NODES + 512));

    hist_kernel<<<(E_EDGES + 255) / 256, 256>>>(ei);
    scan_kernel<<<1, 1024>>>();
    scatter_kernel<<<(E_EDGES + 255) / 256, 256>>>(ei, ea);

    gemm1_fused_kernel<<<(N_NODES + 127) / 128, 512,
                         G1_SMEM_FLOATS * sizeof(float)>>>(x, W1, b1);
    finalize_kernel<<<1, 256>>>(gamma, beta, W2, b2);
    gemm2_kernel<<<(N_NODES + 127) / 128, 256, G2_SMEM_FLOATS * sizeof(float)>>>(out);
}